// round 12
// baseline (speedup 1.0000x reference)
#include <cuda_runtime.h>
#include <cuda_fp16.h>
#include <cstdint>

#define B_ANCH 2048
#define P_POS  4
#define D_DIM  256            // K
#define NNEG   32768
#define ALPHA  0.1f
#define EPSN   1e-12f
#define INV_T  20.0f          // 1/temperature
#define K2E    28.85390081777927f   // 20 * log2(e)
#define SHIFT2 8.0f                 // sum exp2(logit2 - 8)

#define MT     128            // anchors per CTA
#define NB     64             // negatives per tile
#define NTILE  (NNEG / NB)    // 512
#define MBLKS  (B_ANCH / MT)  // 16
#define NGRP   27             // grid 16*27 = 432 CTAs (~3/SM)
#define STR    272            // smem row stride bytes

#define A_BYTES (MT * STR)          // 34816
#define B_BYTES (NB * STR)          // 17408
#define SMEM_TOTAL (A_BYTES + 2 * B_BYTES)   // 69632 -> occ 3

// ---- scratch ----
__device__ uint8_t g_a8[B_ANCH * D_DIM];      // e4m3
__device__ uint8_t g_n8[NNEG * D_DIM];        // e4m3
__device__ float g_pos[B_ANCH * P_POS];
__device__ float g_part[NGRP * B_ANCH];       // [gp][anchor]

// ================= helpers =================
__device__ __forceinline__ uint32_t smem_u32(const void* p) {
    uint32_t a;
    asm("{ .reg .u64 t; cvta.to.shared.u64 t, %1; cvt.u32.u64 %0, t; }" : "=r"(a) : "l"(p));
    return a;
}
__device__ __forceinline__ void cp_async16(uint32_t dst, const void* src) {
    asm volatile("cp.async.cg.shared.global [%0], [%1], 16;" :: "r"(dst), "l"(src) : "memory");
}
#define CP_COMMIT() asm volatile("cp.async.commit_group;" ::: "memory")
#define CP_WAIT(n)  asm volatile("cp.async.wait_group %0;" :: "n"(n) : "memory")

__device__ __forceinline__ uint32_t pack_e4m3_4(float x, float y, float z, float w) {
    uint16_t lo, hi;
    asm("cvt.rn.satfinite.e4m3x2.f32 %0, %1, %2;" : "=h"(lo) : "f"(y), "f"(x));
    asm("cvt.rn.satfinite.e4m3x2.f32 %0, %1, %2;" : "=h"(hi) : "f"(w), "f"(z));
    return (uint32_t)lo | ((uint32_t)hi << 16);
}

__device__ __forceinline__ void mma_fp8_h(uint32_t* c, const uint32_t* a,
                                          uint32_t b0, uint32_t b1) {
    asm volatile(
        "mma.sync.aligned.m16n8k32.row.col.f16.e4m3.e4m3.f16 "
        "{%0,%1}, {%2,%3,%4,%5}, {%6,%7}, {%0,%1};\n"
        : "+r"(c[0]), "+r"(c[1])
        : "r"(a[0]), "r"(a[1]), "r"(a[2]), "r"(a[3]), "r"(b0), "r"(b1));
}

__device__ __forceinline__ void ldsm_x4(uint32_t& r0, uint32_t& r1,
                                        uint32_t& r2, uint32_t& r3, uint32_t a) {
    asm volatile("ldmatrix.sync.aligned.m8n8.x4.shared.b16 {%0,%1,%2,%3}, [%4];"
                 : "=r"(r0), "=r"(r1), "=r"(r2), "=r"(r3) : "r"(a));
}

// ============================================================
// Kernel 1: fused prep — 2 tasks per warp (doubled MLP)
// tasks: [0, B+N) normalize, [B+N, B+N+B*P) pos.  43008 tasks,
// pairs never straddle the boundary (B+N even).
// ============================================================
__global__ void prep_kernel(const float* __restrict__ anch,
                            const float* __restrict__ pos,
                            const float* __restrict__ neg) {
    int warp = threadIdx.x >> 5, lane = threadIdx.x & 31;
    int id0 = (blockIdx.x * 8 + warp) * 2;
    int id1 = id0 + 1;

    if (id0 < B_ANCH + NNEG) {
        // ---- dual normalize ----
        const float* s0; uint8_t* d0;
        const float* s1; uint8_t* d1;
        if (id0 < B_ANCH) { s0 = anch + (size_t)id0 * D_DIM; d0 = g_a8 + (size_t)id0 * D_DIM; }
        else { int r = id0 - B_ANCH; s0 = neg + (size_t)r * D_DIM; d0 = g_n8 + (size_t)r * D_DIM; }
        if (id1 < B_ANCH) { s1 = anch + (size_t)id1 * D_DIM; d1 = g_a8 + (size_t)id1 * D_DIM; }
        else { int r = id1 - B_ANCH; s1 = neg + (size_t)r * D_DIM; d1 = g_n8 + (size_t)r * D_DIM; }

        const float4* p0 = (const float4*)s0;
        const float4* p1 = (const float4*)s1;
        float4 a0 = p0[lane], a1 = p0[lane + 32];
        float4 b0 = p1[lane], b1 = p1[lane + 32];
        float ss0 = a0.x*a0.x + a0.y*a0.y + a0.z*a0.z + a0.w*a0.w
                  + a1.x*a1.x + a1.y*a1.y + a1.z*a1.z + a1.w*a1.w;
        float ss1 = b0.x*b0.x + b0.y*b0.y + b0.z*b0.z + b0.w*b0.w
                  + b1.x*b1.x + b1.y*b1.y + b1.z*b1.z + b1.w*b1.w;
        #pragma unroll
        for (int o = 16; o; o >>= 1) {
            ss0 += __shfl_xor_sync(0xFFFFFFFFu, ss0, o);
            ss1 += __shfl_xor_sync(0xFFFFFFFFu, ss1, o);
        }
        float i0 = 1.0f / fmaxf(sqrtf(ss0), EPSN);
        float i1 = 1.0f / fmaxf(sqrtf(ss1), EPSN);
        uint32_t* w0 = (uint32_t*)d0;
        uint32_t* w1 = (uint32_t*)d1;
        w0[lane]      = pack_e4m3_4(a0.x*i0, a0.y*i0, a0.z*i0, a0.w*i0);
        w0[lane + 32] = pack_e4m3_4(a1.x*i0, a1.y*i0, a1.z*i0, a1.w*i0);
        w1[lane]      = pack_e4m3_4(b0.x*i1, b0.y*i1, b0.z*i1, b0.w*i1);
        w1[lane + 32] = pack_e4m3_4(b1.x*i1, b1.y*i1, b1.z*i1, b1.w*i1);
    } else {
        // ---- dual pos_sim (exact fp32) ----
        int pid0 = id0 - (B_ANCH + NNEG);
        int pid1 = pid0 + 1;
        int ba = pid0 >> 2, bb = pid1 >> 2;
        const float4* A0 = (const float4*)(anch + (size_t)ba * D_DIM);
        const float4* A1 = (const float4*)(anch + (size_t)bb * D_DIM);
        const float4* P0 = (const float4*)(pos  + (size_t)pid0 * D_DIM);
        const float4* P1 = (const float4*)(pos  + (size_t)pid1 * D_DIM);
        float4 xa0 = A0[lane], xa1 = A0[lane + 32];
        float4 xp0 = P0[lane], xp1 = P0[lane + 32];
        float4 ya0 = A1[lane], ya1 = A1[lane + 32];
        float4 yp0 = P1[lane], yp1 = P1[lane + 32];

        float d0 = xa0.x*xp0.x + xa0.y*xp0.y + xa0.z*xp0.z + xa0.w*xp0.w
                 + xa1.x*xp1.x + xa1.y*xp1.y + xa1.z*xp1.z + xa1.w*xp1.w;
        float qa0 = xa0.x*xa0.x + xa0.y*xa0.y + xa0.z*xa0.z + xa0.w*xa0.w
                  + xa1.x*xa1.x + xa1.y*xa1.y + xa1.z*xa1.z + xa1.w*xa1.w;
        float qp0 = xp0.x*xp0.x + xp0.y*xp0.y + xp0.z*xp0.z + xp0.w*xp0.w
                  + xp1.x*xp1.x + xp1.y*xp1.y + xp1.z*xp1.z + xp1.w*xp1.w;
        float d1 = ya0.x*yp0.x + ya0.y*yp0.y + ya0.z*yp0.z + ya0.w*yp0.w
                 + ya1.x*yp1.x + ya1.y*yp1.y + ya1.z*yp1.z + ya1.w*yp1.w;
        float qa1 = ya0.x*ya0.x + ya0.y*ya0.y + ya0.z*ya0.z + ya0.w*ya0.w
                  + ya1.x*ya1.x + ya1.y*ya1.y + ya1.z*ya1.z + ya1.w*ya1.w;
        float qp1 = yp0.x*yp0.x + yp0.y*yp0.y + yp0.z*yp0.z + yp0.w*yp0.w
                  + yp1.x*yp1.x + yp1.y*yp1.y + yp1.z*yp1.z + yp1.w*yp1.w;
        #pragma unroll
        for (int o = 16; o; o >>= 1) {
            d0  += __shfl_xor_sync(0xFFFFFFFFu, d0,  o);
            qa0 += __shfl_xor_sync(0xFFFFFFFFu, qa0, o);
            qp0 += __shfl_xor_sync(0xFFFFFFFFu, qp0, o);
            d1  += __shfl_xor_sync(0xFFFFFFFFu, d1,  o);
            qa1 += __shfl_xor_sync(0xFFFFFFFFu, qa1, o);
            qp1 += __shfl_xor_sync(0xFFFFFFFFu, qp1, o);
        }
        if (lane == 0) {
            g_pos[pid0] = d0 / (fmaxf(sqrtf(qa0), EPSN) * fmaxf(sqrtf(qp0), EPSN)) * INV_T;
            g_pos[pid1] = d1 / (fmaxf(sqrtf(qa1), EPSN) * fmaxf(sqrtf(qp1), EPSN)) * INV_T;
        }
    }
}

// ============================================================
// Kernel 2: fp8 mma.sync GEMM (128x64 tiles), 2-stage, occ 3
// ============================================================
extern __shared__ uint8_t smem_raw[];

__global__ void __launch_bounds__(256, 3) gemm_lse_kernel() {
    uint8_t* sA = smem_raw;
    uint32_t sA_u = smem_u32(smem_raw);
    int tid = threadIdx.x;
    int w = tid >> 5, lane = tid & 31, g = lane >> 2, q = lane & 3;
    int m  = blockIdx.x & 15;
    int gp = blockIdx.x >> 4;           // 0..26
    int m0 = m * MT;
    int tstart = gp * 19;               // 512 = 26*19 + 18
    int tcnt   = (gp == 26) ? 18 : 19;

    const __half2 k2h = __float2half2_rn(K2E);
    const __half2 c8h = __float2half2_rn(-SHIFT2);

    uint32_t ldsm_off = (uint32_t)((((lane >> 4) & 1) * 8 + (lane & 7)) * STR
                                   + ((lane >> 3) & 1) * 16);

    // ---- A tile (32KB) ----
    {
        const uint8_t* gA = g_a8 + (size_t)m0 * D_DIM;
        #pragma unroll
        for (int i = 0; i < 8; i++) {
            int c = tid + i * 256;
            int r = c >> 4, c16 = c & 15;
            cp_async16(sA_u + r * STR + c16 * 16, gA + (size_t)r * 256 + c16 * 16);
        }
    }
    CP_COMMIT();

    // ---- preload B tile 0 (16KB) ----
    {
        const uint8_t* gB = g_n8 + (size_t)tstart * NB * D_DIM;
        uint32_t sB_u = sA_u + A_BYTES;
        #pragma unroll
        for (int i = 0; i < 4; i++) {
            int c = tid + i * 256;
            int r = c >> 4, c16 = c & 15;
            cp_async16(sB_u + r * STR + c16 * 16, gB + (size_t)r * 256 + c16 * 16);
        }
    }
    CP_COMMIT();

    // ---- A fragments -> registers ----
    CP_WAIT(1);
    __syncthreads();
    uint32_t areg[32];
    {
        const uint8_t* r0 = sA + (size_t)(w * 16 + g) * STR;
        const uint8_t* r1 = r0 + 8 * STR;
        #pragma unroll
        for (int ks = 0; ks < 8; ks++) {
            int k0 = ks * 32;
            areg[4*ks+0] = *(const uint32_t*)(r0 + k0 + 4*q);
            areg[4*ks+1] = *(const uint32_t*)(r1 + k0 + 4*q);
            areg[4*ks+2] = *(const uint32_t*)(r0 + k0 + 16 + 4*q);
            areg[4*ks+3] = *(const uint32_t*)(r1 + k0 + 16 + 4*q);
        }
    }

    float rs0 = 0.0f, rs1 = 0.0f;

    for (int t = 0; t < tcnt; t++) {
        CP_WAIT(0);
        __syncthreads();

        // prefetch tile t+1 into the other buffer
        if (t + 1 < tcnt) {
            const uint8_t* gB = g_n8 + (size_t)(tstart + t + 1) * NB * D_DIM;
            uint32_t sB_u = sA_u + A_BYTES + ((t + 1) & 1) * B_BYTES;
            #pragma unroll
            for (int i = 0; i < 4; i++) {
                int c = tid + i * 256;
                int r = c >> 4, c16 = c & 15;
                cp_async16(sB_u + r * STR + c16 * 16, gB + (size_t)r * 256 + c16 * 16);
            }
            CP_COMMIT();
        }

        uint32_t sB_base = sA_u + A_BYTES + (t & 1) * B_BYTES + ldsm_off;
        uint32_t acc[8][2];
        #pragma unroll
        for (int j = 0; j < 8; j++) { acc[j][0] = 0u; acc[j][1] = 0u; }

        #pragma unroll
        for (int ks = 0; ks < 8; ks++) {
            uint32_t kb = sB_base + ks * 32;
            #pragma unroll
            for (int jj = 0; jj < 4; jj++) {
                uint32_t b00, b01, b10, b11;
                ldsm_x4(b00, b01, b10, b11, kb + jj * (16 * STR));
                mma_fp8_h(acc[2*jj],     areg + 4*ks, b00, b01);
                mma_fp8_h(acc[2*jj + 1], areg + 4*ks, b10, b11);
            }
        }

        // half2 epilogue: += exp2(acc*K2E - 8)
        __half2 hs0 = __float2half2_rn(0.0f);
        __half2 hs1 = __float2half2_rn(0.0f);
        #pragma unroll
        for (int j = 0; j < 8; j++) {
            __half2 a0 = *(__half2*)&acc[j][0];
            __half2 a1 = *(__half2*)&acc[j][1];
            hs0 = __hadd2(hs0, h2exp2(__hfma2(a0, k2h, c8h)));
            hs1 = __hadd2(hs1, h2exp2(__hfma2(a1, k2h, c8h)));
        }
        float2 f0 = __half22float2(hs0);
        float2 f1 = __half22float2(hs1);
        rs0 += f0.x + f0.y;
        rs1 += f1.x + f1.y;
    }

    // quad-reduce (cols), write per-row partials
    rs0 += __shfl_xor_sync(0xFFFFFFFFu, rs0, 1);
    rs0 += __shfl_xor_sync(0xFFFFFFFFu, rs0, 2);
    rs1 += __shfl_xor_sync(0xFFFFFFFFu, rs1, 1);
    rs1 += __shfl_xor_sync(0xFFFFFFFFu, rs1, 2);
    if (q == 0) {
        int row = m0 + w * 16 + g;
        g_part[(size_t)gp * B_ANCH + row]     = rs0;
        g_part[(size_t)gp * B_ANCH + row + 8] = rs1;
    }
}

// ============================================================
// Kernel 3: finalize — single block, 1024 threads, 2 anchors each
// lse = 8*ln2 + log(sum)
// ============================================================
__global__ void finalize_kernel(const int* __restrict__ counts,
                                float* __restrict__ out) {
    __shared__ float red[1024];
    int tid = threadIdx.x;
    float local = 0.0f;

    #pragma unroll
    for (int bb = 0; bb < 2; bb++) {
        int b = tid + bb * 1024;
        float s = 0.0f;
        #pragma unroll
        for (int c = 0; c < NGRP; c++) s += g_part[(size_t)c * B_ANCH + b];
        float lse = 5.545177444479562f + logf(s);
        int cnt = counts[b];
        float ps[4];
        #pragma unroll
        for (int j = 0; j < 4; j++) ps[j] = g_pos[b * 4 + j];

        #pragma unroll
        for (int j = 0; j < 4; j++) {
            if (j < cnt) {
                float mx = fmaxf(ps[j], lse);
                local += mx + log1pf(expf(fminf(ps[j], lse) - mx)) - ps[j];
            }
        }
        float mx = fmaxf(fmaxf(ps[0], ps[1]), fmaxf(ps[2], ps[3]));
        float e0 = expf(ps[0] - mx), e1 = expf(ps[1] - mx);
        float e2 = expf(ps[2] - mx), e3 = expf(ps[3] - mx);
        float wps = (e0*ps[0] + e1*ps[1] + e2*ps[2] + e3*ps[3]) / (e0 + e1 + e2 + e3);
        if (cnt > 1) {
            float m2 = fmaxf(wps, lse);
            local += ALPHA * (m2 + log1pf(expf(fminf(wps, lse) - m2)) - wps);
        }
    }

    red[tid] = local;
    __syncthreads();
    #pragma unroll
    for (int o = 512; o; o >>= 1) {
        if (tid < o) red[tid] += red[tid + o];
        __syncthreads();
    }
    if (tid == 0) out[0] = red[0] / (float)B_ANCH;
}

// ============================================================
extern "C" void kernel_launch(void* const* d_in, const int* in_sizes, int n_in,
                              void* d_out, int out_size) {
    const float* anch   = (const float*)d_in[0];
    const float* pos    = (const float*)d_in[1];
    const float* neg    = (const float*)d_in[2];
    const int*   counts = (const int*)d_in[3];
    float* out = (float*)d_out;

    cudaFuncSetAttribute(gemm_lse_kernel,
                         cudaFuncAttributeMaxDynamicSharedMemorySize, SMEM_TOTAL);

    prep_kernel<<<(B_ANCH + NNEG + B_ANCH * P_POS) / 16, 256>>>(anch, pos, neg);
    gemm_lse_kernel<<<MBLKS * NGRP, 256, SMEM_TOTAL>>>();
    finalize_kernel<<<1, 1024>>>(counts, out);
}

// round 13
// speedup vs baseline: 1.0457x; 1.0457x over previous
#include <cuda_runtime.h>
#include <cuda_fp16.h>
#include <cstdint>

#define B_ANCH 2048
#define P_POS  4
#define D_DIM  256            // K
#define NNEG   32768
#define ALPHA  0.1f
#define EPSN   1e-12f
#define INV_T  20.0f          // 1/temperature
#define K2E    28.85390081777927f   // 20 * log2(e)
#define SHIFT2 8.0f                 // sum exp2(logit2 - 8)

#define MT     128            // anchors per CTA
#define NB     128            // negatives per tile
#define MBLKS  (B_ANCH / MT)  // 16
#define NGRP   18             // grid 16*18 = 288 CTAs
#define STR    272            // smem row stride bytes

#define A_BYTES (MT * STR)          // 34816
#define B_BYTES (NB * STR)          // 34816
#define SMEM_TOTAL (A_BYTES + 2 * B_BYTES)   // 104448 -> occ 2

#define NORM_BLOCKS ((B_ANCH + NNEG) / 32)   // 1088
#define POS_BLOCKS  (B_ANCH * P_POS / 8)     // 1024

// ---- scratch ----
__device__ uint8_t g_a8[B_ANCH * D_DIM];      // e4m3
__device__ uint8_t g_n8[NNEG * D_DIM];        // e4m3
__device__ float g_pos[B_ANCH * P_POS];
__device__ float g_part[NGRP * B_ANCH];       // [gp][anchor]

// ================= helpers =================
__device__ __forceinline__ uint32_t smem_u32(const void* p) {
    uint32_t a;
    asm("{ .reg .u64 t; cvta.to.shared.u64 t, %1; cvt.u32.u64 %0, t; }" : "=r"(a) : "l"(p));
    return a;
}
__device__ __forceinline__ void cp_async16(uint32_t dst, const void* src) {
    asm volatile("cp.async.cg.shared.global [%0], [%1], 16;" :: "r"(dst), "l"(src) : "memory");
}
#define CP_COMMIT() asm volatile("cp.async.commit_group;" ::: "memory")
#define CP_WAIT(n)  asm volatile("cp.async.wait_group %0;" :: "n"(n) : "memory")

__device__ __forceinline__ uint32_t pack_e4m3_4(float x, float y, float z, float w) {
    uint16_t lo, hi;
    asm("cvt.rn.satfinite.e4m3x2.f32 %0, %1, %2;" : "=h"(lo) : "f"(y), "f"(x));
    asm("cvt.rn.satfinite.e4m3x2.f32 %0, %1, %2;" : "=h"(hi) : "f"(w), "f"(z));
    return (uint32_t)lo | ((uint32_t)hi << 16);
}

__device__ __forceinline__ void mma_fp8_h(uint32_t* c, const uint32_t* a,
                                          uint32_t b0, uint32_t b1) {
    asm volatile(
        "mma.sync.aligned.m16n8k32.row.col.f16.e4m3.e4m3.f16 "
        "{%0,%1}, {%2,%3,%4,%5}, {%6,%7}, {%0,%1};\n"
        : "+r"(c[0]), "+r"(c[1])
        : "r"(a[0]), "r"(a[1]), "r"(a[2]), "r"(a[3]), "r"(b0), "r"(b1));
}

__device__ __forceinline__ void ldsm_x4(uint32_t& r0, uint32_t& r1,
                                        uint32_t& r2, uint32_t& r3, uint32_t a) {
    asm volatile("ldmatrix.sync.aligned.m8n8.x4.shared.b16 {%0,%1,%2,%3}, [%4];"
                 : "=r"(r0), "=r"(r1), "=r"(r2), "=r"(r3) : "r"(a));
}

// ============================================================
// Kernel 1: prep — normalize (8 threads/row, MLP 8) + pos tail
// blocks [0, NORM_BLOCKS): 32 rows each; then POS_BLOCKS pos blocks
// ============================================================
__global__ void prep_kernel(const float* __restrict__ anch,
                            const float* __restrict__ pos,
                            const float* __restrict__ neg) {
    if (blockIdx.x < NORM_BLOCKS) {
        int tid = threadIdx.x;
        int rloc = tid >> 3, sub = tid & 7;
        int row = blockIdx.x * 32 + rloc;
        const float* src;
        uint8_t* dst;
        if (row < B_ANCH) {
            src = anch + (size_t)row * D_DIM;  dst = g_a8 + (size_t)row * D_DIM;
        } else {
            int r = row - B_ANCH;
            src = neg + (size_t)r * D_DIM;     dst = g_n8 + (size_t)r * D_DIM;
        }
        const float4* s4 = (const float4*)src;
        float4 v[8];
        #pragma unroll
        for (int i = 0; i < 8; i++) v[i] = s4[sub + 8 * i];   // coalesced
        float ss = 0.0f;
        #pragma unroll
        for (int i = 0; i < 8; i++)
            ss += v[i].x*v[i].x + v[i].y*v[i].y + v[i].z*v[i].z + v[i].w*v[i].w;
        ss += __shfl_xor_sync(0xFFFFFFFFu, ss, 1);
        ss += __shfl_xor_sync(0xFFFFFFFFu, ss, 2);
        ss += __shfl_xor_sync(0xFFFFFFFFu, ss, 4);
        float inv = 1.0f / fmaxf(sqrtf(ss), EPSN);
        uint32_t* d32 = (uint32_t*)dst;
        #pragma unroll
        for (int i = 0; i < 8; i++)
            d32[sub + 8 * i] = pack_e4m3_4(v[i].x*inv, v[i].y*inv, v[i].z*inv, v[i].w*inv);
    } else {
        // ---- pos_sim: one warp per pair (exact fp32) ----
        int warp = threadIdx.x >> 5, lane = threadIdx.x & 31;
        int pid = (blockIdx.x - NORM_BLOCKS) * 8 + warp;
        int b = pid >> 2;
        const float4* a4 = (const float4*)(anch + (size_t)b * D_DIM);
        const float4* p4 = (const float4*)(pos  + (size_t)pid * D_DIM);
        float4 a0 = a4[lane], a1 = a4[lane + 32];
        float4 p0 = p4[lane], p1 = p4[lane + 32];
        float dot = a0.x*p0.x + a0.y*p0.y + a0.z*p0.z + a0.w*p0.w
                  + a1.x*p1.x + a1.y*p1.y + a1.z*p1.z + a1.w*p1.w;
        float asq = a0.x*a0.x + a0.y*a0.y + a0.z*a0.z + a0.w*a0.w
                  + a1.x*a1.x + a1.y*a1.y + a1.z*a1.z + a1.w*a1.w;
        float psq = p0.x*p0.x + p0.y*p0.y + p0.z*p0.z + p0.w*p0.w
                  + p1.x*p1.x + p1.y*p1.y + p1.z*p1.z + p1.w*p1.w;
        #pragma unroll
        for (int o = 16; o; o >>= 1) {
            dot += __shfl_xor_sync(0xFFFFFFFFu, dot, o);
            asq += __shfl_xor_sync(0xFFFFFFFFu, asq, o);
            psq += __shfl_xor_sync(0xFFFFFFFFu, psq, o);
        }
        if (lane == 0) {
            float denom = fmaxf(sqrtf(asq), EPSN) * fmaxf(sqrtf(psq), EPSN);
            g_pos[pid] = dot / denom * INV_T;
        }
    }
}

// ============================================================
// Kernel 2: fp8 mma.sync GEMM (128x128 tiles), 2-stage cp.async
// (identical to R11 — measured optimum)
// ============================================================
extern __shared__ uint8_t smem_raw[];

__global__ void __launch_bounds__(256, 2) gemm_lse_kernel() {
    uint8_t* sA = smem_raw;
    uint32_t sA_u = smem_u32(smem_raw);
    int tid = threadIdx.x;
    int w = tid >> 5, lane = tid & 31, g = lane >> 2, q = lane & 3;
    int m  = blockIdx.x & 15;
    int gp = blockIdx.x >> 4;
    int m0 = m * MT;
    int tstart = gp * 14 + min(gp, 4);      // 256 = 4*15 + 14*14
    int tcnt   = 14 + (gp < 4 ? 1 : 0);

    const __half2 k2h = __float2half2_rn(K2E);
    const __half2 c8h = __float2half2_rn(-SHIFT2);

    uint32_t ldsm_off = (uint32_t)((((lane >> 4) & 1) * 8 + (lane & 7)) * STR
                                   + ((lane >> 3) & 1) * 16);

    // ---- A tile (32KB) ----
    {
        const uint8_t* gA = g_a8 + (size_t)m0 * D_DIM;
        #pragma unroll
        for (int i = 0; i < 8; i++) {
            int c = tid + i * 256;
            int r = c >> 4, c16 = c & 15;
            cp_async16(sA_u + r * STR + c16 * 16, gA + (size_t)r * 256 + c16 * 16);
        }
    }
    CP_COMMIT();

    // ---- preload B tile 0 (32KB) ----
    {
        const uint8_t* gB = g_n8 + (size_t)tstart * NB * D_DIM;
        uint32_t sB_u = sA_u + A_BYTES;
        #pragma unroll
        for (int i = 0; i < 8; i++) {
            int c = tid + i * 256;
            int r = c >> 4, c16 = c & 15;
            cp_async16(sB_u + r * STR + c16 * 16, gB + (size_t)r * 256 + c16 * 16);
        }
    }
    CP_COMMIT();

    // ---- A fragments -> registers ----
    CP_WAIT(1);
    __syncthreads();
    uint32_t areg[32];
    {
        const uint8_t* r0 = sA + (size_t)(w * 16 + g) * STR;
        const uint8_t* r1 = r0 + 8 * STR;
        #pragma unroll
        for (int ks = 0; ks < 8; ks++) {
            int k0 = ks * 32;
            areg[4*ks+0] = *(const uint32_t*)(r0 + k0 + 4*q);
            areg[4*ks+1] = *(const uint32_t*)(r1 + k0 + 4*q);
            areg[4*ks+2] = *(const uint32_t*)(r0 + k0 + 16 + 4*q);
            areg[4*ks+3] = *(const uint32_t*)(r1 + k0 + 16 + 4*q);
        }
    }

    float rs0 = 0.0f, rs1 = 0.0f;

    for (int t = 0; t < tcnt; t++) {
        CP_WAIT(0);
        __syncthreads();

        if (t + 1 < tcnt) {
            const uint8_t* gB = g_n8 + (size_t)(tstart + t + 1) * NB * D_DIM;
            uint32_t sB_u = sA_u + A_BYTES + ((t + 1) & 1) * B_BYTES;
            #pragma unroll
            for (int i = 0; i < 8; i++) {
                int c = tid + i * 256;
                int r = c >> 4, c16 = c & 15;
                cp_async16(sB_u + r * STR + c16 * 16, gB + (size_t)r * 256 + c16 * 16);
            }
            CP_COMMIT();
        }

        uint32_t sB_base = sA_u + A_BYTES + (t & 1) * B_BYTES + ldsm_off;
        uint32_t acc[16][2];
        #pragma unroll
        for (int j = 0; j < 16; j++) { acc[j][0] = 0u; acc[j][1] = 0u; }

        #pragma unroll
        for (int ks = 0; ks < 8; ks++) {
            uint32_t kb = sB_base + ks * 32;
            #pragma unroll
            for (int jj = 0; jj < 8; jj++) {
                uint32_t b00, b01, b10, b11;
                ldsm_x4(b00, b01, b10, b11, kb + jj * (16 * STR));
                mma_fp8_h(acc[2*jj],     areg + 4*ks, b00, b01);
                mma_fp8_h(acc[2*jj + 1], areg + 4*ks, b10, b11);
            }
        }

        __half2 hs0 = __float2half2_rn(0.0f);
        __half2 hs1 = __float2half2_rn(0.0f);
        #pragma unroll
        for (int j = 0; j < 16; j++) {
            __half2 a0 = *(__half2*)&acc[j][0];
            __half2 a1 = *(__half2*)&acc[j][1];
            hs0 = __hadd2(hs0, h2exp2(__hfma2(a0, k2h, c8h)));
            hs1 = __hadd2(hs1, h2exp2(__hfma2(a1, k2h, c8h)));
        }
        float2 f0 = __half22float2(hs0);
        float2 f1 = __half22float2(hs1);
        rs0 += f0.x + f0.y;
        rs1 += f1.x + f1.y;
    }

    rs0 += __shfl_xor_sync(0xFFFFFFFFu, rs0, 1);
    rs0 += __shfl_xor_sync(0xFFFFFFFFu, rs0, 2);
    rs1 += __shfl_xor_sync(0xFFFFFFFFu, rs1, 1);
    rs1 += __shfl_xor_sync(0xFFFFFFFFu, rs1, 2);
    if (q == 0) {
        int row = m0 + w * 16 + g;
        g_part[(size_t)gp * B_ANCH + row]     = rs0;
        g_part[(size_t)gp * B_ANCH + row + 8] = rs1;
    }
}

// ============================================================
// Kernel 3: finalize — single block, 1024 threads, 2 anchors each
// lse = 8*ln2 + log(sum)
// ============================================================
__global__ void finalize_kernel(const int* __restrict__ counts,
                                float* __restrict__ out) {
    __shared__ float red[1024];
    int tid = threadIdx.x;
    float local = 0.0f;

    #pragma unroll
    for (int bb = 0; bb < 2; bb++) {
        int b = tid + bb * 1024;
        float s = 0.0f;
        #pragma unroll
        for (int c = 0; c < NGRP; c++) s += g_part[(size_t)c * B_ANCH + b];
        float lse = 5.545177444479562f + logf(s);
        int cnt = counts[b];
        float ps[4];
        #pragma unroll
        for (int j = 0; j < 4; j++) ps[j] = g_pos[b * 4 + j];

        #pragma unroll
        for (int j = 0; j < 4; j++) {
            if (j < cnt) {
                float mx = fmaxf(ps[j], lse);
                local += mx + log1pf(expf(fminf(ps[j], lse) - mx)) - ps[j];
            }
        }
        float mx = fmaxf(fmaxf(ps[0], ps[1]), fmaxf(ps[2], ps[3]));
        float e0 = expf(ps[0] - mx), e1 = expf(ps[1] - mx);
        float e2 = expf(ps[2] - mx), e3 = expf(ps[3] - mx);
        float wps = (e0*ps[0] + e1*ps[1] + e2*ps[2] + e3*ps[3]) / (e0 + e1 + e2 + e3);
        if (cnt > 1) {
            float m2 = fmaxf(wps, lse);
            local += ALPHA * (m2 + log1pf(expf(fminf(wps, lse) - m2)) - wps);
        }
    }

    red[tid] = local;
    __syncthreads();
    #pragma unroll
    for (int o = 512; o; o >>= 1) {
        if (tid < o) red[tid] += red[tid + o];
        __syncthreads();
    }
    if (tid == 0) out[0] = red[0] / (float)B_ANCH;
}

// ============================================================
extern "C" void kernel_launch(void* const* d_in, const int* in_sizes, int n_in,
                              void* d_out, int out_size) {
    const float* anch   = (const float*)d_in[0];
    const float* pos    = (const float*)d_in[1];
    const float* neg    = (const float*)d_in[2];
    const int*   counts = (const int*)d_in[3];
    float* out = (float*)d_out;

    cudaFuncSetAttribute(gemm_lse_kernel,
                         cudaFuncAttributeMaxDynamicSharedMemorySize, SMEM_TOTAL);

    prep_kernel<<<NORM_BLOCKS + POS_BLOCKS, 256>>>(anch, pos, neg);
    gemm_lse_kernel<<<MBLKS * NGRP, 256, SMEM_TOTAL>>>();
    finalize_kernel<<<1, 1024>>>(counts, out);
}